// round 2
// baseline (speedup 1.0000x reference)
#include <cuda_runtime.h>
#include <cstdint>
#include <cstdio>

// Problem shape (fixed by the reference).
constexpr int B = 4096;
constexpr int K = 64;
constexpr int D = 512;      // 128 float4 per row
constexpr int VOCAB = 32000;

// Flag: 1 if impls buffer is int64, 0 if int32. Written by probe kernel.
__device__ int g_idx_is_64 = 0;

// ---------------------------------------------------------------------------
// Probe: decide index width. int64 little-endian values in [0,32000) have all
// odd 32-bit words == 0. For int32 data those words are random indices;
// P(128 consecutive zeros) ~ (1/32000)^128 ~ 0. Reads stay in the first 256
// words, in-bounds under either layout (B*K = 262144 elements minimum).
// ---------------------------------------------------------------------------
__global__ void probe_idx_dtype(const int* __restrict__ impls_raw) {
    if (threadIdx.x == 0) {
        int is64 = 1;
        for (int i = 1; i < 256; i += 2) {
            if (impls_raw[i] != 0) { is64 = 0; break; }
        }
        g_idx_is_64 = is64;
    }
}

// ---------------------------------------------------------------------------
// Main kernel: one block per batch row b.
//   smem: vectors[b,:] staged once (2 KB), reused for all 64 gathers.
//   8 warps x 8 k's each; 2 embed rows (8 independent float4 loads) in
//   flight per warp iteration to cover L2 latency.
// Output (float32):
//   with_impls==1: out[0:B*K] = impls, out[B*K:2*B*K] = scores
//   with_impls==0: out[0:B*K] = scores
// Indices are clamped so a dtype misread can never fault — it shows up as
// rel_err instead.
// ---------------------------------------------------------------------------
__global__ __launch_bounds__(256) void selector_kernel(
    const float*  __restrict__ vectors,
    const int*    __restrict__ impls_raw,
    const float*  __restrict__ table,
    float*        __restrict__ out,
    int with_impls)
{
    __shared__ float4 sv[D / 4];   // 128 float4 = 2 KB

    const int b    = blockIdx.x;
    const int tid  = threadIdx.x;
    const int warp = tid >> 5;
    const int lane = tid & 31;

    const float4* vrow = reinterpret_cast<const float4*>(vectors + (size_t)b * D);
    if (tid < D / 4) sv[tid] = vrow[tid];
    __syncthreads();

    float4 v0 = sv[0 * 32 + lane];
    float4 v1 = sv[1 * 32 + lane];
    float4 v2 = sv[2 * 32 + lane];
    float4 v3 = sv[3 * 32 + lane];

    const int is64 = g_idx_is_64;
    const long long* impls64 = reinterpret_cast<const long long*>(impls_raw);

    const size_t base = (size_t)b * K;
    float* scores_out = out + (with_impls ? (size_t)B * K : 0);

    #pragma unroll
    for (int kk = 0; kk < 8; kk += 2) {
        const int k0 = warp * 8 + kk;
        const int k1 = k0 + 1;

        long long raw0, raw1;
        if (is64) {
            raw0 = impls64[base + k0];
            raw1 = impls64[base + k1];
        } else {
            raw0 = impls_raw[base + k0];
            raw1 = impls_raw[base + k1];
        }
        // Defensive clamp: bad index -> wrong value (rel_err), never a fault.
        long long idx0 = raw0 < 0 ? 0 : (raw0 >= VOCAB ? VOCAB - 1 : raw0);
        long long idx1 = raw1 < 0 ? 0 : (raw1 >= VOCAB ? VOCAB - 1 : raw1);

        const float4* r0 = reinterpret_cast<const float4*>(table + (size_t)idx0 * D);
        const float4* r1 = reinterpret_cast<const float4*>(table + (size_t)idx1 * D);

        float4 a0 = r0[0 * 32 + lane];
        float4 a1 = r0[1 * 32 + lane];
        float4 a2 = r0[2 * 32 + lane];
        float4 a3 = r0[3 * 32 + lane];
        float4 c0 = r1[0 * 32 + lane];
        float4 c1 = r1[1 * 32 + lane];
        float4 c2 = r1[2 * 32 + lane];
        float4 c3 = r1[3 * 32 + lane];

        float acc0 = a0.x * v0.x + a0.y * v0.y + a0.z * v0.z + a0.w * v0.w;
        acc0      += a1.x * v1.x + a1.y * v1.y + a1.z * v1.z + a1.w * v1.w;
        acc0      += a2.x * v2.x + a2.y * v2.y + a2.z * v2.z + a2.w * v2.w;
        acc0      += a3.x * v3.x + a3.y * v3.y + a3.z * v3.z + a3.w * v3.w;

        float acc1 = c0.x * v0.x + c0.y * v0.y + c0.z * v0.z + c0.w * v0.w;
        acc1      += c1.x * v1.x + c1.y * v1.y + c1.z * v1.z + c1.w * v1.w;
        acc1      += c2.x * v2.x + c2.y * v2.y + c2.z * v2.z + c2.w * v2.w;
        acc1      += c3.x * v3.x + c3.y * v3.y + c3.z * v3.z + c3.w * v3.w;

        #pragma unroll
        for (int o = 16; o > 0; o >>= 1) {
            acc0 += __shfl_down_sync(0xffffffffu, acc0, o);
            acc1 += __shfl_down_sync(0xffffffffu, acc1, o);
        }

        if (lane == 0) {
            if (with_impls) {
                out[base + k0] = (float)raw0;
                out[base + k1] = (float)raw1;
            }
            scores_out[base + k0] = acc0;
            scores_out[base + k1] = acc1;
        }
    }
}

extern "C" void kernel_launch(void* const* d_in, const int* in_sizes, int n_in,
                              void* d_out, int out_size)
{
    // One-line forensics on every call; harmless, host-side, not captured as
    // a graph node. Shows up in the error log if the bench fails.
    fprintf(stderr, "[klaunch] n_in=%d sizes={%d,%d,%d} out_size=%d\n",
            n_in,
            n_in > 0 ? in_sizes[0] : -1,
            n_in > 1 ? in_sizes[1] : -1,
            n_in > 2 ? in_sizes[2] : -1,
            out_size);

    const float* vectors   = (const float*)d_in[0];
    const int*   impls_raw = (const int*)  d_in[1];
    const float* table     = (const float*)d_in[2];
    float*       out       = (float*)d_out;

    const int with_impls = (out_size >= 2 * B * K) ? 1 : 0;

    probe_idx_dtype<<<1, 32>>>(impls_raw);
    selector_kernel<<<B, 256>>>(vectors, impls_raw, table, out, with_impls);
}

// round 3
// speedup vs baseline: 1.0963x; 1.0963x over previous
#include <cuda_runtime.h>
#include <cstdint>

// Problem shape (fixed by the reference).
constexpr int B = 4096;
constexpr int K = 64;
constexpr int D = 512;      // 128 float4 per row
constexpr int VOCAB = 32000;

// ---------------------------------------------------------------------------
// One block per batch row b. 8 warps x 8 k's each, 2 embed rows (8 independent
// float4 loads) in flight per warp iteration.
//
// Index dtype is detected inline per-warp: lanes sample odd 32-bit words
// 1..63 of the impls buffer. int64 little-endian values in [0,32000) have all
// odd words == 0; for int32 data P(all 32 samples zero) ~ (1/32000)^32 ~ 0.
// The sampled 256 B region is L2-broadcast across blocks (negligible traffic)
// and in-bounds under either layout.
//
// Output (float32): out[0:B*K] = impls (as float), out[B*K:2*B*K] = scores.
// If out_size indicates a scores-only buffer, impls writes are skipped.
// Indices are clamped so a misread can never fault.
// ---------------------------------------------------------------------------
__global__ __launch_bounds__(256) void selector_kernel(
    const float*  __restrict__ vectors,
    const int*    __restrict__ impls_raw,
    const float*  __restrict__ table,
    float*        __restrict__ out,
    int with_impls)
{
    __shared__ float4 sv[D / 4];   // 128 float4 = 2 KB

    const int b    = blockIdx.x;
    const int tid  = threadIdx.x;
    const int warp = tid >> 5;
    const int lane = tid & 31;

    // ---- inline index-dtype probe (all warps, ~1 cached load + ballot) ----
    const int sample = impls_raw[2 * lane + 1];          // odd words 1..63
    const unsigned nz = __ballot_sync(0xffffffffu, sample != 0);
    const int is64 = (nz == 0u);

    // ---- stage query vector ----
    const float4* vrow = reinterpret_cast<const float4*>(vectors + (size_t)b * D);
    if (tid < D / 4) sv[tid] = vrow[tid];

    // ---- preload this warp's 8 indices (lanes 0-7), while smem fills ----
    const size_t base = (size_t)b * K;
    const long long* impls64 = reinterpret_cast<const long long*>(impls_raw);

    int myidx = 0;
    if (lane < 8) {
        const size_t p = base + (size_t)warp * 8 + lane;
        myidx = is64 ? (int)impls64[p] : impls_raw[p];
        if (with_impls) out[p] = (float)myidx;           // impls passthrough
    }

    __syncthreads();

    float4 v0 = sv[0 * 32 + lane];
    float4 v1 = sv[1 * 32 + lane];
    float4 v2 = sv[2 * 32 + lane];
    float4 v3 = sv[3 * 32 + lane];

    float* scores_out = out + (with_impls ? (size_t)B * K : 0);

    #pragma unroll
    for (int kk = 0; kk < 8; kk += 2) {
        // Broadcast this iteration's two indices from the holding lanes.
        int i0 = __shfl_sync(0xffffffffu, myidx, kk);
        int i1 = __shfl_sync(0xffffffffu, myidx, kk + 1);
        // Defensive clamp: bad index -> wrong value (rel_err), never a fault.
        i0 = i0 < 0 ? 0 : (i0 >= VOCAB ? VOCAB - 1 : i0);
        i1 = i1 < 0 ? 0 : (i1 >= VOCAB ? VOCAB - 1 : i1);

        const float4* r0 = reinterpret_cast<const float4*>(table + (size_t)i0 * D);
        const float4* r1 = reinterpret_cast<const float4*>(table + (size_t)i1 * D);

        // 8 independent loads in flight before any FMA consumes them.
        float4 a0 = r0[0 * 32 + lane];
        float4 a1 = r0[1 * 32 + lane];
        float4 a2 = r0[2 * 32 + lane];
        float4 a3 = r0[3 * 32 + lane];
        float4 c0 = r1[0 * 32 + lane];
        float4 c1 = r1[1 * 32 + lane];
        float4 c2 = r1[2 * 32 + lane];
        float4 c3 = r1[3 * 32 + lane];

        float acc0 = a0.x * v0.x + a0.y * v0.y + a0.z * v0.z + a0.w * v0.w;
        acc0      += a1.x * v1.x + a1.y * v1.y + a1.z * v1.z + a1.w * v1.w;
        acc0      += a2.x * v2.x + a2.y * v2.y + a2.z * v2.z + a2.w * v2.w;
        acc0      += a3.x * v3.x + a3.y * v3.y + a3.z * v3.z + a3.w * v3.w;

        float acc1 = c0.x * v0.x + c0.y * v0.y + c0.z * v0.z + c0.w * v0.w;
        acc1      += c1.x * v1.x + c1.y * v1.y + c1.z * v1.z + c1.w * v1.w;
        acc1      += c2.x * v2.x + c2.y * v2.y + c2.z * v2.z + c2.w * v2.w;
        acc1      += c3.x * v3.x + c3.y * v3.y + c3.z * v3.z + c3.w * v3.w;

        #pragma unroll
        for (int o = 16; o > 0; o >>= 1) {
            acc0 += __shfl_down_sync(0xffffffffu, acc0, o);
            acc1 += __shfl_down_sync(0xffffffffu, acc1, o);
        }

        if (lane == 0) {
            scores_out[base + warp * 8 + kk]     = acc0;
            scores_out[base + warp * 8 + kk + 1] = acc1;
        }
    }
}

extern "C" void kernel_launch(void* const* d_in, const int* in_sizes, int n_in,
                              void* d_out, int out_size)
{
    const float* vectors   = (const float*)d_in[0];
    const int*   impls_raw = (const int*)  d_in[1];
    const float* table     = (const float*)d_in[2];
    float*       out       = (float*)d_out;

    const int with_impls = (out_size >= 2 * B * K) ? 1 : 0;

    selector_kernel<<<B, 256>>>(vectors, impls_raw, table, out, with_impls);
}